// round 1
// baseline (speedup 1.0000x reference)
#include <cuda_runtime.h>
#include <cuda_bf16.h>
#include <cstddef>

// Problem constants
#define S_TOT  8192
#define HID    1152
#define NH     16
#define HD     72
#define NSEG   8
#define LSEG   1024
#define H3     3456
#define ATT_SCALE 0.11785113019775793f   // 72^-0.5

// Scratch (allocation-free rule: __device__ globals)
__device__ float g_qkv[(size_t)S_TOT * H3];   // 113 MB
__device__ float g_ctx[(size_t)S_TOT * HID];  // 37.7 MB

// ---------------------------------------------------------------------------
// SGEMM with fused bias: C[M,N] = A[M,K] @ B[K,N] + bias[N]
// 128x128 block tile, BK=8, 256 threads, 8x8 per thread, register prefetch.
// ---------------------------------------------------------------------------
__global__ __launch_bounds__(256, 2) void sgemm_bias(
    const float* __restrict__ A, const float* __restrict__ B,
    const float* __restrict__ bias, float* __restrict__ C,
    int M, int N, int K)
{
    __shared__ float As[8][128];
    __shared__ float Bs[8][128];

    const int t  = threadIdx.x;
    const int tx = t & 15;
    const int ty = t >> 4;
    const int m0 = blockIdx.y * 128;
    const int n0 = blockIdx.x * 128;

    const int arow = t >> 1;          // 0..127
    const int acol = (t & 1) << 2;    // 0 or 4
    const int brow = t >> 5;          // 0..7
    const int bcol = (t & 31) << 2;   // 0..124

    const float* Ap = A + (size_t)(m0 + arow) * K + acol;
    const float* Bp = B + (size_t)brow * N + n0 + bcol;

    float acc[8][8];
#pragma unroll
    for (int i = 0; i < 8; i++)
#pragma unroll
        for (int j = 0; j < 8; j++) acc[i][j] = 0.f;

    float4 av = *(const float4*)Ap;
    float4 bv = *(const float4*)Bp;

    for (int k0 = 0; k0 < K; k0 += 8) {
        As[acol + 0][arow] = av.x;
        As[acol + 1][arow] = av.y;
        As[acol + 2][arow] = av.z;
        As[acol + 3][arow] = av.w;
        *(float4*)(&Bs[brow][bcol]) = bv;
        __syncthreads();

        if (k0 + 8 < K) {
            av = *(const float4*)(Ap + k0 + 8);
            bv = *(const float4*)(Bp + (size_t)(k0 + 8) * N);
        }

#pragma unroll
        for (int kk = 0; kk < 8; kk++) {
            float4 a0 = *(const float4*)(&As[kk][ty * 4]);
            float4 a1 = *(const float4*)(&As[kk][64 + ty * 4]);
            float4 b0 = *(const float4*)(&Bs[kk][tx * 4]);
            float4 b1 = *(const float4*)(&Bs[kk][64 + tx * 4]);
            float a[8] = {a0.x, a0.y, a0.z, a0.w, a1.x, a1.y, a1.z, a1.w};
            float b[8] = {b0.x, b0.y, b0.z, b0.w, b1.x, b1.y, b1.z, b1.w};
#pragma unroll
            for (int i = 0; i < 8; i++)
#pragma unroll
                for (int j = 0; j < 8; j++) acc[i][j] += a[i] * b[j];
        }
        __syncthreads();
    }

    float bb[8];
#pragma unroll
    for (int j = 0; j < 4; j++) {
        bb[j]     = bias[n0 + tx * 4 + j];
        bb[4 + j] = bias[n0 + 64 + tx * 4 + j];
    }

#pragma unroll
    for (int i = 0; i < 8; i++) {
        int row = m0 + ((i < 4) ? (ty * 4 + i) : (64 + ty * 4 + (i - 4)));
        float* Cp = C + (size_t)row * N + n0;
        float4 v0 = make_float4(acc[i][0] + bb[0], acc[i][1] + bb[1],
                                acc[i][2] + bb[2], acc[i][3] + bb[3]);
        float4 v1 = make_float4(acc[i][4] + bb[4], acc[i][5] + bb[5],
                                acc[i][6] + bb[6], acc[i][7] + bb[7]);
        *(float4*)(Cp + tx * 4)      = v0;
        *(float4*)(Cp + 64 + tx * 4) = v1;
    }
}

// ---------------------------------------------------------------------------
// RoPE applied in-place to the Q and K sections of g_qkv.
// rotate_half: for d<36: q'[d]=q[d]*c - q[d+36]*s ; q'[d+36]=q[d+36]*c + q[d]*s
// cos/sin are pre-tiled over segments: index by global position s.
// cos[s, d] == cos[s, d+36] (emb = concat(freqs,freqs)), so read only d<36.
// ---------------------------------------------------------------------------
__global__ void rope_kernel(float* __restrict__ qkv,
                            const float* __restrict__ cosb,
                            const float* __restrict__ sinb)
{
    int idx = blockIdx.x * blockDim.x + threadIdx.x;   // S*NH*36
    if (idx >= S_TOT * NH * (HD / 2)) return;
    int d   = idx % (HD / 2);
    int tmp = idx / (HD / 2);
    int h   = tmp % NH;
    int s   = tmp / NH;

    float c  = cosb[s * HD + d];
    float sn = sinb[s * HD + d];

    size_t base = (size_t)s * H3 + h * HD + d;

    float q0 = qkv[base], q1 = qkv[base + HD / 2];
    qkv[base]          = q0 * c - q1 * sn;
    qkv[base + HD / 2] = q1 * c + q0 * sn;

    float k0 = qkv[base + HID], k1 = qkv[base + HID + HD / 2];
    qkv[base + HID]          = k0 * c - k1 * sn;
    qkv[base + HID + HD / 2] = k1 * c + k0 * sn;
}

// ---------------------------------------------------------------------------
// Flash attention: one block per (seg, head, 64-query tile).
// BQ=64 queries, BK=32 keys per inner tile, 256 threads, online softmax.
// Smem: Q 64x73 + K 32x73 + V 32x73 + P 64x33 + stats = 45.3 KB (static).
// ---------------------------------------------------------------------------
#define BQ 64
#define BKT 32

__global__ __launch_bounds__(256) void attn_kernel(const float* __restrict__ qkv,
                                                   float* __restrict__ ctx)
{
    __shared__ float sQ[BQ][HD + 1];
    __shared__ float sK[BKT][HD + 1];
    __shared__ float sV[BKT][HD + 1];
    __shared__ float sP[BQ][BKT + 1];
    __shared__ float sAlpha[BQ];
    __shared__ float sL[BQ];

    const int t   = threadIdx.x;
    const int qt  = blockIdx.x;   // 0..15
    const int h   = blockIdx.y;   // 0..15
    const int seg = blockIdx.z;   // 0..7

    const int sbase = seg * LSEG;
    const int qbase = sbase + qt * BQ;

    // Load Q tile (scaled)
    for (int idx = t; idx < BQ * HD; idx += 256) {
        int r = idx / HD, d = idx % HD;
        sQ[r][d] = qkv[(size_t)(qbase + r) * H3 + h * HD + d] * ATT_SCALE;
    }

    const int tx = t & 15;   // k-col group (2 cols)
    const int ty = t >> 4;   // q-row group (4 rows)

    float m_i[4], l_i[4];
#pragma unroll
    for (int i = 0; i < 4; i++) { m_i[i] = -1e30f; l_i[i] = 0.f; }

    // O-phase mapping: 2 rows x 9 cols per thread
    const int orow = (t >> 3) * 2;      // 0,2,...,62
    const int ocol = (t & 7) * 9;       // 0,9,...,63
    float o[2][9];
#pragma unroll
    for (int r = 0; r < 2; r++)
#pragma unroll
        for (int j = 0; j < 9; j++) o[r][j] = 0.f;

    for (int kt = 0; kt < LSEG / BKT; kt++) {
        __syncthreads();   // previous O-phase done with sK/sV/sP
        const int kbase = sbase + kt * BKT;
        for (int idx = t; idx < BKT * HD; idx += 256) {
            int r = idx / HD, d = idx % HD;
            size_t g = (size_t)(kbase + r) * H3 + h * HD + d;
            sK[r][d] = qkv[g + HID];
            sV[r][d] = qkv[g + 2 * HID];
        }
        __syncthreads();

        // ---- S = Q K^T (per thread: 4 rows x 2 cols) ----
        float acc[4][2] = {{0.f, 0.f}, {0.f, 0.f}, {0.f, 0.f}, {0.f, 0.f}};
#pragma unroll 8
        for (int d = 0; d < HD; d++) {
            float b0 = sK[tx * 2][d];
            float b1 = sK[tx * 2 + 1][d];
#pragma unroll
            for (int i = 0; i < 4; i++) {
                float a = sQ[ty * 4 + i][d];
                acc[i][0] += a * b0;
                acc[i][1] += a * b1;
            }
        }

        // ---- online softmax (row reductions over 16 tx lanes) ----
#pragma unroll
        for (int i = 0; i < 4; i++) {
            float tmax = fmaxf(acc[i][0], acc[i][1]);
#pragma unroll
            for (int off = 8; off >= 1; off >>= 1)
                tmax = fmaxf(tmax, __shfl_xor_sync(0xffffffffu, tmax, off));
            float mnew  = fmaxf(m_i[i], tmax);
            float alpha = __expf(m_i[i] - mnew);
            float p0 = __expf(acc[i][0] - mnew);
            float p1 = __expf(acc[i][1] - mnew);
            sP[ty * 4 + i][tx * 2]     = p0;
            sP[ty * 4 + i][tx * 2 + 1] = p1;
            float ps = p0 + p1;
#pragma unroll
            for (int off = 8; off >= 1; off >>= 1)
                ps += __shfl_xor_sync(0xffffffffu, ps, off);
            l_i[i] = l_i[i] * alpha + ps;
            m_i[i] = mnew;
            if (tx == 0) {
                sAlpha[ty * 4 + i] = alpha;
                sL[ty * 4 + i]     = l_i[i];
            }
        }
        __syncthreads();

        // ---- O = alpha*O + P @ V ----
        float al0 = sAlpha[orow];
        float al1 = sAlpha[orow + 1];
#pragma unroll
        for (int j = 0; j < 9; j++) { o[0][j] *= al0; o[1][j] *= al1; }
#pragma unroll 4
        for (int k = 0; k < BKT; k++) {
            float p0 = sP[orow][k];
            float p1 = sP[orow + 1][k];
#pragma unroll
            for (int j = 0; j < 9; j++) {
                float v = sV[k][ocol + j];
                o[0][j] += p0 * v;
                o[1][j] += p1 * v;
            }
        }
    }

    float inv0 = 1.f / sL[orow];
    float inv1 = 1.f / sL[orow + 1];
    size_t ob0 = (size_t)(qbase + orow) * HID + h * HD + ocol;
#pragma unroll
    for (int j = 0; j < 9; j++) {
        ctx[ob0 + j]       = o[0][j] * inv0;
        ctx[ob0 + HID + j] = o[1][j] * inv1;
    }
}

// ---------------------------------------------------------------------------
// Launch: QKV GEMM -> RoPE -> attention -> out GEMM
// ---------------------------------------------------------------------------
extern "C" void kernel_launch(void* const* d_in, const int* in_sizes, int n_in,
                              void* d_out, int out_size)
{
    const float* hidden = (const float*)d_in[0];   // [1,8192,1152]
    const float* cosb   = (const float*)d_in[1];   // [8192,72]
    const float* sinb   = (const float*)d_in[2];   // [8192,72]
    const float* Wqkv   = (const float*)d_in[3];   // [1152,3456]
    const float* bqkv   = (const float*)d_in[4];   // [3456]
    const float* Wout   = (const float*)d_in[5];   // [1152,1152]
    const float* bout   = (const float*)d_in[6];   // [1152]
    // d_in[7] = cu_seqlens (fixed uniform segmentation; unused)
    float* out = (float*)d_out;                    // [1,8192,1152] f32

    float *qkv, *ctx;
    cudaGetSymbolAddress((void**)&qkv, g_qkv);
    cudaGetSymbolAddress((void**)&ctx, g_ctx);

    // 1) QKV projection + bias
    dim3 g1(H3 / 128, S_TOT / 128);
    sgemm_bias<<<g1, 256>>>(hidden, Wqkv, bqkv, qkv, S_TOT, H3, HID);

    // 2) RoPE in-place on Q,K
    int nrope = S_TOT * NH * (HD / 2);
    rope_kernel<<<(nrope + 255) / 256, 256>>>(qkv, cosb, sinb);

    // 3) Segmented attention
    dim3 ga(LSEG / BQ, NH, NSEG);
    attn_kernel<<<ga, 256>>>(qkv, ctx);

    // 4) Output projection + bias
    dim3 g2(HID / 128, S_TOT / 128);
    sgemm_bias<<<g2, 256>>>(ctx, Wout, bout, out, S_TOT, HID, HID);
}